// round 13
// baseline (speedup 1.0000x reference)
#include <cuda_runtime.h>
#include <math.h>

// ---------------------------------------------------------------------------
// MS-SSIM, 5 levels, 16x3x512x512 fp32 (48 planes). 3 launches:
//   ssim_band0 : level 0 as 32-wide x 128-tall rolling bands (4 chunks of 32
//                rows, mod-42 ring) + fused pool pyramid L1..L4.
//   ssim_rest  : level 1 as 128-tall bands + levels 2..4 as tiles, one grid.
//   final      : parallel weighted combine; re-zeros d_sums.
// Blur: 2 packed f32x2 streams (x,y) and (x^2+y^2, x*y), all fp32.
// Band halo (10 rows) is loaded/h-blurred once per band: -18% load+hblur work.
// ---------------------------------------------------------------------------

typedef unsigned long long u64;

__device__ __forceinline__ u64 pack2(float lo, float hi) {
    u64 r; asm("mov.b64 %0,{%1,%2};" : "=l"(r) : "f"(lo), "f"(hi)); return r;
}
__device__ __forceinline__ void unpack2(u64 v, float& lo, float& hi) {
    asm("mov.b64 {%0,%1},%2;" : "=f"(lo), "=f"(hi) : "l"(v));
}
__device__ __forceinline__ u64 fma2(u64 a, u64 b, u64 c) {
    u64 d; asm("fma.rn.f32x2 %0,%1,%2,%3;" : "=l"(d) : "l"(a), "l"(b), "l"(c)); return d;
}
__device__ __forceinline__ u64 mul2(u64 a, u64 b) {
    u64 d; asm("mul.rn.f32x2 %0,%1,%2;" : "=l"(d) : "l"(a), "l"(b)); return d;
}
__device__ __forceinline__ u64 add2(u64 a, u64 b) {
    u64 d; asm("add.rn.f32x2 %0,%1,%2;" : "=l"(d) : "l"(a), "l"(b)); return d;
}
__device__ __forceinline__ float sqrt_fast(float x) {
    float r; asm("sqrt.approx.f32 %0,%1;" : "=f"(r) : "f"(x)); return r;
}

#define TW 32
#define TH 32
#define EH 42
#define EW 42
#define SIN_S 44
#define SH_S  33

#define G_0 0.00102838f
#define G_1 0.00759876f
#define G_2 0.03600088f
#define G_3 0.10936090f
#define G_4 0.21300530f
#define G_5 0.26601160f

__device__ __align__(16) float d_Xp[4177920];
__device__ __align__(16) float d_Yp[4177920];
__device__ float d_sums[480];   // [level][img][2]  (zero-init; final re-zeros)

#define OFF1 0
#define OFF2 3145728
#define OFF3 3932160
#define OFF4 4128768

#define C1V 1e-4f
#define C2V 9e-4f

// ===========================================================================
// Rolling band worker: 32-wide x 128-tall, 4 chunks of 32 output rows,
// mod-42 row rings. POOL => also emits the L1..L4 pool pyramid (level 0).
// ===========================================================================
template <bool POOL>
__device__ __forceinline__ void ssim_band(
    const float* __restrict__ Xi, const float* __restrict__ Yi,
    int H, int level, int img, int bx, int byy,
    float* __restrict__ Xp, float* __restrict__ Yp)
{
    __shared__ u64 sIN[EH * SIN_S];   // ring: packed (x,y), slot = row mod 42
    __shared__ u64 sMU[EH * SH_S];    // ring: h-blurred (gx,gy)
    __shared__ u64 sSP[EH * SH_S];    // ring: h-blurred (E[xx+yy], E[xy])
    __shared__ u64 sL2[64];
    __shared__ float red[2][8];

    const int W = H;
    const int outH = H - 10;
    const int tx0 = bx * 32;
    const int tid = threadIdx.x;
    const int ty = tid >> 5, tx = tid & 31;
    const bool colint = (tx0 + EW <= W);

    const float gg[11] = {G_0,G_1,G_2,G_3,G_4,G_5,G_4,G_3,G_2,G_1,G_0};
    u64 G2r[11];
#pragma unroll
    for (int k = 0; k < 11; k++) G2r[k] = pack2(gg[k], gg[k]);

    float d_sum = 0.f, cs_sum = 0.f;
    int s0 = (byy * 128) % 42;

    for (int c = 0; c < 4; c++) {
        const int oy = byy * 128 + c * 32;

        // ---- load new input rows into the ring -------------------------------
        {
            const int rstart = c ? (oy + 10) : oy;
            int sstart = c ? (s0 + 10) : s0; if (sstart >= 42) sstart -= 42;
            const int nrows = c ? 32 : 42;
            if (colint) {
                for (int i = tid; i < nrows * 21; i += 256) {
                    int r = i / 21, cc = (i - r * 21) * 2;
                    int gr = rstart + r; if (gr > H - 1) gr = H - 1;
                    int slot = sstart + r; if (slot >= 42) slot -= 42;
                    const float2 lx = *(const float2*)(Xi + (size_t)gr * W + tx0 + cc);
                    const float2 ly = *(const float2*)(Yi + (size_t)gr * W + tx0 + cc);
                    sIN[slot * SIN_S + cc]     = pack2(lx.x, ly.x);
                    sIN[slot * SIN_S + cc + 1] = pack2(lx.y, ly.y);
                }
            } else {
                for (int i = tid; i < nrows * EW; i += 256) {
                    int r = i / EW, cc = i - r * EW;
                    int gr = rstart + r; if (gr > H - 1) gr = H - 1;
                    int gc = tx0 + cc;   if (gc > W - 1) gc = W - 1;
                    int slot = sstart + r; if (slot >= 42) slot -= 42;
                    sIN[slot * SIN_S + cc] =
                        pack2(Xi[(size_t)gr * W + gc], Yi[(size_t)gr * W + gc]);
                }
            }
        }
        __syncthreads();

        // ---- fused pool pyramid: L1 + L2 for this chunk ----------------------
        if (POOL) {
            const u64 QUARTER = pack2(0.25f, 0.25f);
            const int lane = tid & 31;
            int ph = tid >> 4, pw = tid & 15;
            int sl = s0 + 2 * ph;  if (sl  >= 42) sl  -= 42;
            int sl2 = sl + 1;      if (sl2 >= 42) sl2 -= 42;
            const u64* p0 = sIN + sl  * SIN_S + pw * 2;
            const u64* p1 = sIN + sl2 * SIN_S + pw * 2;
            u64 v1 = mul2(add2(add2(p0[0], p0[1]), add2(p1[0], p1[1])), QUARTER);
            {
                float a, b; unpack2(v1, a, b);
                size_t po = (size_t)img * 65536
                          + (size_t)(byy * 64 + c * 16 + ph) * 256 + (bx * 16 + pw);
                (Xp + OFF1)[po] = a; (Yp + OFF1)[po] = b;
            }
            u64 s2v = add2(v1, __shfl_xor_sync(0xffffffffu, v1, 1));
            s2v = add2(s2v, __shfl_xor_sync(0xffffffffu, s2v, 16));
            if ((lane & 17) == 0) {
                u64 v2 = mul2(s2v, QUARTER);
                int qh = tid >> 5, qw = lane >> 1;
                float a, b; unpack2(v2, a, b);
                size_t po = (size_t)img * 16384
                          + (size_t)(byy * 32 + c * 8 + qh) * 128 + (bx * 8 + qw);
                (Xp + OFF2)[po] = a; (Yp + OFF2)[po] = b;
                sL2[qh * 8 + qw] = v2;
            }
        }

        // ---- hblur: only the NEW rows of this chunk --------------------------
        {
            const int start = c ? 10 : 0;
            auto hb = [&](int item) {
                int lr = item >> 3, c4 = (item & 7) << 2;
                int slot = s0 + start + lr; if (slot >= 42) slot -= 42;
                const u64* row = sIN + slot * SIN_S + c4;
                u64 aMU[4] = {0,0,0,0}, aSP[4] = {0,0,0,0};
#pragma unroll
                for (int k = 0; k < 14; k++) {
                    u64 v = row[k];
                    float vx, vy; unpack2(v, vx, vy);
                    u64 sp = pack2(fmaf(vx, vx, vy * vy), vx * vy);
#pragma unroll
                    for (int q = 0; q < 4; q++) {
                        int t = k - q;
                        if (t >= 0 && t < 11) {
                            aMU[q] = fma2(v,  G2r[t], aMU[q]);
                            aSP[q] = fma2(sp, G2r[t], aSP[q]);
                        }
                    }
                }
                int o = slot * SH_S + c4;
#pragma unroll
                for (int q = 0; q < 4; q++) {
                    sMU[o + q] = aMU[q];
                    sSP[o + q] = aSP[q];
                }
            };
            hb(tid);
            if (c == 0 && tid < 336 - 256) hb(tid + 256);
        }
        __syncthreads();

        // ---- pool tail: L3 + L4 for this chunk -------------------------------
        if (POOL && tid < 16) {
            const u64 QUARTER = pack2(0.25f, 0.25f);
            int rh = tid >> 2, rw = tid & 3;
            const u64* q0 = sL2 + (rh * 2) * 8 + rw * 2;
            u64 v3 = mul2(add2(add2(q0[0], q0[1]), add2(q0[8], q0[9])), QUARTER);
            {
                float a, b; unpack2(v3, a, b);
                size_t po = (size_t)img * 4096
                          + (size_t)(byy * 16 + c * 4 + rh) * 64 + (bx * 4 + rw);
                (Xp + OFF3)[po] = a; (Yp + OFF3)[po] = b;
            }
            u64 s4 = add2(v3, __shfl_xor_sync(0xffffu, v3, 1));
            s4 = add2(s4, __shfl_xor_sync(0xffffu, s4, 4));
            if ((tid & 5) == 0) {
                u64 v4 = mul2(s4, QUARTER);
                int sh = tid >> 3, sw = (tid >> 1) & 1;
                float a, b; unpack2(v4, a, b);
                size_t po = (size_t)img * 1024
                          + (size_t)(byy * 8 + c * 2 + sh) * 32 + (bx * 2 + sw);
                (Xp + OFF4)[po] = a; (Yp + OFF4)[po] = b;
            }
        }

        // ---- vblur (4 rows per thread) + epilogue ----------------------------
        {
            const int rbase = ty * 4;
            u64 aMU[4] = {0,0,0,0}, aSP[4] = {0,0,0,0};
            int slot = s0 + rbase; if (slot >= 42) slot -= 42;
#pragma unroll
            for (int k = 0; k < 14; k++) {
                u64 mu = sMU[slot * SH_S + tx];
                u64 sp = sSP[slot * SH_S + tx];
#pragma unroll
                for (int q = 0; q < 4; q++) {
                    int t = k - q;
                    if (t >= 0 && t < 11) {
                        aMU[q] = fma2(mu, G2r[t], aMU[q]);
                        aSP[q] = fma2(sp, G2r[t], aSP[q]);
                    }
                }
                slot++; if (slot == 42) slot = 0;
            }
            const int ocol = tx0 + tx;
#pragma unroll
            for (int q = 0; q < 4; q++) {
                int orow = oy + rbase + q;
                if (orow < outH && ocol < outH) {
                    float mu1, mu2, ess, exy;
                    unpack2(aMU[q], mu1, mu2);
                    unpack2(aSP[q], ess, exy);
                    float mu1sq = mu1 * mu1, mu2sq = mu2 * mu2, mu12 = mu1 * mu2;
                    float sig_sum = ess - mu1sq - mu2sq;
                    float sig12 = exy - mu12;
                    float S1 = __fdividef(2.f * mu12 + C1V, mu1sq + mu2sq + C1V);
                    float S2 = __fdividef(2.f * sig12 + C2V, sig_sum + C2V);
                    float S = fminf(S1 + S2, 2.0f);
                    d_sum += sqrt_fast(2.0f - S);
                    cs_sum += S2;
                }
            }
        }

        s0 += 32; if (s0 >= 42) s0 -= 42;
    }

    // ---- block reduce + atomic ------------------------------------------------
#pragma unroll
    for (int o = 16; o > 0; o >>= 1) {
        d_sum  += __shfl_down_sync(0xffffffffu, d_sum,  o);
        cs_sum += __shfl_down_sync(0xffffffffu, cs_sum, o);
    }
    if (tx == 0) { red[0][ty] = d_sum; red[1][ty] = cs_sum; }
    __syncthreads();
    if (tid == 0) {
        float ds = 0.f, cs = 0.f;
#pragma unroll
        for (int j = 0; j < 8; j++) { ds += red[0][j]; cs += red[1][j]; }
        atomicAdd(&d_sums[(level * 48 + img) * 2 + 0], ds);
        atomicAdd(&d_sums[(level * 48 + img) * 2 + 1], cs);
    }
}

__global__ void __launch_bounds__(256) ssim_band0_kernel(
    const float* __restrict__ X, const float* __restrict__ Y,
    float* __restrict__ Xp, float* __restrict__ Yp)
{
    const int img = blockIdx.z;
    ssim_band<true>(X + (size_t)img * 262144, Y + (size_t)img * 262144,
                    512, 0, img, blockIdx.x, blockIdx.y, Xp, Yp);
}

// ===========================================================================
// Champion tile worker (levels 2..4).
// ===========================================================================
__device__ __forceinline__ void ssim_tile_rest(
    const float* __restrict__ Xi, const float* __restrict__ Yi,
    int H, int level, int img, int bx, int by)
{
    __shared__ u64 sIN[EH * SIN_S];
    __shared__ u64 sMU[EH * SH_S];
    __shared__ u64 sSP[EH * SH_S];
    __shared__ float red[2][8];

    const int W = H;
    const int outH = H - 10;
    const int tx0 = bx * TW;
    const int ty0 = by * TH;
    const int tid = threadIdx.x;

    const float gg[11] = {G_0,G_1,G_2,G_3,G_4,G_5,G_4,G_3,G_2,G_1,G_0};
    u64 G2r[11];
#pragma unroll
    for (int k = 0; k < 11; k++) G2r[k] = pack2(gg[k], gg[k]);

    const bool interior = (tx0 + EW <= W) && (ty0 + EH <= H);
    {
        int r = tid / EW, c = tid - r * EW;
        if (interior) {
            const float* xp = Xi + (size_t)(ty0 + r) * W + (tx0 + c);
            const float* yp = Yi + (size_t)(ty0 + r) * W + (tx0 + c);
            int rr = r, cc = c;
#pragma unroll
            for (int it = 0; it < 7; it++) {
                if (it < 6 || tid < (EH * EW - 6 * 256)) {
                    sIN[rr * SIN_S + cc] = pack2(__ldg(xp), __ldg(yp));
                }
                cc += 4; rr += 6;
                xp += 6 * (size_t)W + 4; yp += 6 * (size_t)W + 4;
                if (cc >= EW) { cc -= EW; rr += 1; xp += W - EW; yp += W - EW; }
            }
        } else {
            for (int i = tid; i < EH * EW; i += 256) {
                int r2 = i / EW, c2 = i - r2 * EW;
                int gr = ty0 + r2; if (gr > H - 1) gr = H - 1;
                int gc = tx0 + c2; if (gc > W - 1) gc = W - 1;
                sIN[r2 * SIN_S + c2] = pack2(Xi[(size_t)gr * W + gc], Yi[(size_t)gr * W + gc]);
            }
        }
    }
    __syncthreads();

    {
        auto hblur = [&](int item) {
            int r = item >> 3, c4 = (item & 7) << 2;
            const u64* row = sIN + r * SIN_S + c4;
            u64 aMU[4] = {0,0,0,0}, aSP[4] = {0,0,0,0};
#pragma unroll
            for (int k = 0; k < 14; k++) {
                u64 v = row[k];
                float vx, vy; unpack2(v, vx, vy);
                u64 sp = pack2(fmaf(vx, vx, vy * vy), vx * vy);
#pragma unroll
                for (int q = 0; q < 4; q++) {
                    int t = k - q;
                    if (t >= 0 && t < 11) {
                        aMU[q] = fma2(v,  G2r[t], aMU[q]);
                        aSP[q] = fma2(sp, G2r[t], aSP[q]);
                    }
                }
            }
            int o = r * SH_S + c4;
#pragma unroll
            for (int q = 0; q < 4; q++) {
                sMU[o + q] = aMU[q];
                sSP[o + q] = aSP[q];
            }
        };
        hblur(tid);
        if (tid < EH * 8 - 256) hblur(tid + 256);
    }
    __syncthreads();

    float d_acc = 0.f, cs_acc = 0.f;
    const int ty = tid >> 5, tx = tid & 31;
    const int rbase = ty * 4;
    {
        u64 aMU[4] = {0,0,0,0}, aSP[4] = {0,0,0,0};
#pragma unroll
        for (int k = 0; k < 14; k++) {
            int row = (rbase + k) * SH_S + tx;
            u64 mu = sMU[row];
            u64 sp = sSP[row];
#pragma unroll
            for (int q = 0; q < 4; q++) {
                int t = k - q;
                if (t >= 0 && t < 11) {
                    aMU[q] = fma2(mu, G2r[t], aMU[q]);
                    aSP[q] = fma2(sp, G2r[t], aSP[q]);
                }
            }
        }
        const int ocol = tx0 + tx;
#pragma unroll
        for (int q = 0; q < 4; q++) {
            int orow = ty0 + rbase + q;
            if (orow < outH && ocol < outH) {
                float mu1, mu2, ess, exy;
                unpack2(aMU[q], mu1, mu2);
                unpack2(aSP[q], ess, exy);
                float mu1sq = mu1 * mu1, mu2sq = mu2 * mu2, mu12 = mu1 * mu2;
                float sig_sum = ess - mu1sq - mu2sq;
                float sig12 = exy - mu12;
                float S1 = __fdividef(2.f * mu12 + C1V, mu1sq + mu2sq + C1V);
                float S2 = __fdividef(2.f * sig12 + C2V, sig_sum + C2V);
                float S = fminf(S1 + S2, 2.0f);
                d_acc += sqrt_fast(2.0f - S);
                cs_acc += S2;
            }
        }
    }

#pragma unroll
    for (int o = 16; o > 0; o >>= 1) {
        d_acc  += __shfl_down_sync(0xffffffffu, d_acc,  o);
        cs_acc += __shfl_down_sync(0xffffffffu, cs_acc, o);
    }
    if (tx == 0) { red[0][ty] = d_acc; red[1][ty] = cs_acc; }
    __syncthreads();
    if (tid == 0) {
        float ds = 0.f, cs = 0.f;
#pragma unroll
        for (int j = 0; j < 8; j++) { ds += red[0][j]; cs += red[1][j]; }
        atomicAdd(&d_sums[(level * 48 + img) * 2 + 0], ds);
        atomicAdd(&d_sums[(level * 48 + img) * 2 + 1], cs);
    }
}

// level 1 as bands (blocks 0..767) + levels 2..4 as tiles (768..1775)
__global__ void __launch_bounds__(256) ssim_rest_kernel(
    const float* __restrict__ Xp, const float* __restrict__ Yp)
{
    int b = blockIdx.x;
    if (b < 768) {
        int img = b >> 4;
        int t = b & 15;
        int byy = t >> 3;
        int bx = t & 7;
        const float* Xi = Xp + OFF1 + (size_t)img * 65536;
        const float* Yi = Yp + OFF1 + (size_t)img * 65536;
        ssim_band<false>(Xi, Yi, 256, 1, img, bx, byy, nullptr, nullptr);
        return;
    }
    b -= 768;
    int level, H, nt, off;
    if (b < 768)      { level = 2; H = 128; nt = 4; off = OFF2; }
    else if (b < 960) { level = 3; H = 64;  nt = 2; off = OFF3; b -= 768; }
    else              { level = 4; H = 32;  nt = 1; off = OFF4; b -= 960; }
    if (level == 2) { /* b already correct */ }
    int tiles = nt * nt;
    int img = b / tiles;
    int t = b - img * tiles;
    int by = t / nt;
    int bx = t - by * nt;
    const float* Xi = Xp + off + (size_t)img * H * H;
    const float* Yi = Yp + off + (size_t)img * H * H;
    ssim_tile_rest(Xi, Yi, H, level, img, bx, by);
}

__global__ void final_kernel(float* out, int out_size)
{
    __shared__ float part[2];
    const int i = threadIdx.x;       // 64 threads
    const float wts[5]  = {0.0448f, 0.2856f, 0.3001f, 0.2363f, 0.1333f};
    const float icnt[5] = {1.f/252004.f, 1.f/60516.f, 1.f/13924.f, 1.f/2916.f, 1.f/484.f};
    float v = 0.f;
    if (i < 48) {
        v = 1.f;
#pragma unroll
        for (int l = 0; l < 4; l++) {
            float csm = fmaxf(d_sums[(l * 48 + i) * 2 + 1] * icnt[l], 0.f);
            v *= __powf(csm, wts[l]);
        }
        float dm = fmaxf(d_sums[(4 * 48 + i) * 2 + 0] * icnt[4], 0.f);
        v *= __powf(dm, wts[4]);
    }
    float s = v;
#pragma unroll
    for (int o = 16; o > 0; o >>= 1) s += __shfl_down_sync(0xffffffffu, s, o);
    if ((i & 31) == 0) part[i >> 5] = s;
    __syncthreads();
    if (i == 0) {
        float r = (part[0] + part[1]) * (1.0f / 48.0f);
        for (int k = 0; k < out_size; k++) out[k] = r;
    }
    // restore invariant: d_sums zeroed for the next kernel_launch call
    __syncthreads();
    for (int j = i; j < 480; j += 64) d_sums[j] = 0.f;
}

extern "C" void kernel_launch(void* const* d_in, const int* in_sizes, int n_in,
                              void* d_out, int out_size)
{
    const float* X = (const float*)d_in[0];
    const float* Y = (const float*)d_in[1];
    float* out = (float*)d_out;

    float *Xp = nullptr, *Yp = nullptr;
    cudaGetSymbolAddress((void**)&Xp, d_Xp);
    cudaGetSymbolAddress((void**)&Yp, d_Yp);

    ssim_band0_kernel<<<dim3(16, 4, 48), 256>>>(X, Y, Xp, Yp);
    ssim_rest_kernel<<<1776, 256>>>(Xp, Yp);
    final_kernel<<<1, 64>>>(out, out_size);
}

// round 14
// speedup vs baseline: 1.1422x; 1.1422x over previous
#include <cuda_runtime.h>
#include <math.h>

// ---------------------------------------------------------------------------
// MS-SSIM, 5 levels, 16x3x512x512 fp32 (48 planes). 3 launches:
//   ssim_level0 (+ fused pool pyramid L1..L4), ssim_rest (levels 1..4),
//   final (parallel combine + re-zero of d_sums).
// R14: NO sIN staging. hblur reads its 14-value windows directly from global
// (L1-resident tile) via float4 __ldg; pool reads global float2. Removes the
// load-phase STS + conflicted hblur LDS from the binding l1tex pipe (~-35%
// wavefronts/block), drops SMEM to 22KB, one less barrier.
// Blur: 2 packed f32x2 streams (x,y) and (x^2+y^2, x*y), all fp32.
// ---------------------------------------------------------------------------

typedef unsigned long long u64;

__device__ __forceinline__ u64 pack2(float lo, float hi) {
    u64 r; asm("mov.b64 %0,{%1,%2};" : "=l"(r) : "f"(lo), "f"(hi)); return r;
}
__device__ __forceinline__ void unpack2(u64 v, float& lo, float& hi) {
    asm("mov.b64 {%0,%1},%2;" : "=f"(lo), "=f"(hi) : "l"(v));
}
__device__ __forceinline__ u64 fma2(u64 a, u64 b, u64 c) {
    u64 d; asm("fma.rn.f32x2 %0,%1,%2,%3;" : "=l"(d) : "l"(a), "l"(b), "l"(c)); return d;
}
__device__ __forceinline__ u64 mul2(u64 a, u64 b) {
    u64 d; asm("mul.rn.f32x2 %0,%1,%2;" : "=l"(d) : "l"(a), "l"(b)); return d;
}
__device__ __forceinline__ u64 add2(u64 a, u64 b) {
    u64 d; asm("add.rn.f32x2 %0,%1,%2;" : "=l"(d) : "l"(a), "l"(b)); return d;
}
__device__ __forceinline__ float sqrt_fast(float x) {
    float r; asm("sqrt.approx.f32 %0,%1;" : "=f"(r) : "f"(x)); return r;
}

#define TW 32
#define TH 32
#define EH 42
#define EW 42
#define SH_S  33       // stride of h-blurred maps

// gaussian(sigma=1.5, 11 taps), normalized
#define G_0 0.00102838f
#define G_1 0.00759876f
#define G_2 0.03600088f
#define G_3 0.10936090f
#define G_4 0.21300530f
#define G_5 0.26601160f

__device__ __align__(16) float d_Xp[4177920];
__device__ __align__(16) float d_Yp[4177920];
__device__ float d_sums[480];   // [level][img][2]  (zero-init; final re-zeros)

#define OFF1 0
#define OFF2 3145728
#define OFF3 3932160
#define OFF4 4128768

#define C1V 1e-4f
#define C2V 9e-4f

// core tile worker. POOL => level 0 (H=512, also emits L1..L4 pyramid).
template <bool POOL>
__device__ __forceinline__ void ssim_tile(
    const float* __restrict__ Xi, const float* __restrict__ Yi,
    int H, int level, int img, int bx, int by,
    float* __restrict__ Xp, float* __restrict__ Yp)
{
    __shared__ u64 sMU[EH * SH_S];    // h-blurred (gx,gy)
    __shared__ u64 sSP[EH * SH_S];    // h-blurred (E[xx+yy], E[xy])
    __shared__ u64 sL2[64];
    __shared__ float red[2][8];

    const int W = H;
    const int outH = H - 10;
    const int tx0 = bx * TW;
    const int ty0 = by * TH;
    const int tid = threadIdx.x;

    const float gg[11] = {G_0,G_1,G_2,G_3,G_4,G_5,G_4,G_3,G_2,G_1,G_0};
    u64 G2r[11];
#pragma unroll
    for (int k = 0; k < 11; k++) G2r[k] = pack2(gg[k], gg[k]);

    // ---- fused pool pyramid (level 0 only): L1, L2 (reads global, L1-hot) ---
    if (POOL) {
        const u64 QUARTER = pack2(0.25f, 0.25f);
        const int lane = tid & 31;
        int ph = tid >> 4, pw = tid & 15;
        const float* xr = Xi + (size_t)(ty0 + 2 * ph) * W + tx0 + 2 * pw;
        const float* yr = Yi + (size_t)(ty0 + 2 * ph) * W + tx0 + 2 * pw;
        float2 a0 = __ldg((const float2*)xr);
        float2 a1 = __ldg((const float2*)(xr + W));
        float2 b0 = __ldg((const float2*)yr);
        float2 b1 = __ldg((const float2*)(yr + W));
        float px = 0.25f * ((a0.x + a0.y) + (a1.x + a1.y));
        float py = 0.25f * ((b0.x + b0.y) + (b1.x + b1.y));
        u64 v1 = pack2(px, py);
        {
            size_t po = (size_t)img * 65536 + (size_t)(by * 16 + ph) * 256 + (bx * 16 + pw);
            (Xp + OFF1)[po] = px; (Yp + OFF1)[po] = py;
        }
        u64 s2 = add2(v1, __shfl_xor_sync(0xffffffffu, v1, 1));
        s2 = add2(s2, __shfl_xor_sync(0xffffffffu, s2, 16));
        if ((lane & 17) == 0) {
            u64 v2 = mul2(s2, QUARTER);
            int qh = tid >> 5, qw = lane >> 1;
            float a, b; unpack2(v2, a, b);
            size_t po = (size_t)img * 16384 + (size_t)(by * 8 + qh) * 128 + (bx * 8 + qw);
            (Xp + OFF2)[po] = a; (Yp + OFF2)[po] = b;
            sL2[qh * 8 + qw] = v2;
        }
    }

    // ---- horizontal blur straight from global: 42 rows x 8 groups of 4 ------
    const bool interior = (tx0 + 44 <= W) && (ty0 + EH <= H);
    if (interior) {
        auto hblur = [&](int item) {
            int r = item >> 3, c4 = (item & 7) << 2;
            const float4* xr = (const float4*)(Xi + (size_t)(ty0 + r) * W + tx0 + c4);
            const float4* yr = (const float4*)(Yi + (size_t)(ty0 + r) * W + tx0 + c4);
            float xs[16], ys[16];
#pragma unroll
            for (int j = 0; j < 4; j++) {
                float4 xv = __ldg(xr + j);
                float4 yv = __ldg(yr + j);
                xs[4*j+0] = xv.x; xs[4*j+1] = xv.y; xs[4*j+2] = xv.z; xs[4*j+3] = xv.w;
                ys[4*j+0] = yv.x; ys[4*j+1] = yv.y; ys[4*j+2] = yv.z; ys[4*j+3] = yv.w;
            }
            u64 aMU[4] = {0,0,0,0}, aSP[4] = {0,0,0,0};
#pragma unroll
            for (int k = 0; k < 14; k++) {
                float vx = xs[k], vy = ys[k];
                u64 v  = pack2(vx, vy);
                u64 sp = pack2(fmaf(vx, vx, vy * vy), vx * vy);
#pragma unroll
                for (int q = 0; q < 4; q++) {
                    int t = k - q;
                    if (t >= 0 && t < 11) {
                        aMU[q] = fma2(v,  G2r[t], aMU[q]);
                        aSP[q] = fma2(sp, G2r[t], aSP[q]);
                    }
                }
            }
            int o = r * SH_S + c4;
#pragma unroll
            for (int q = 0; q < 4; q++) {
                sMU[o + q] = aMU[q];
                sSP[o + q] = aSP[q];
            }
        };
        hblur(tid);
        if (tid < EH * 8 - 256) hblur(tid + 256);
    } else {
        auto hblur_g = [&](int item) {
            int r = item >> 3, c4 = (item & 7) << 2;
            int gr = ty0 + r; if (gr > H - 1) gr = H - 1;
            const float* xr = Xi + (size_t)gr * W;
            const float* yr = Yi + (size_t)gr * W;
            u64 aMU[4] = {0,0,0,0}, aSP[4] = {0,0,0,0};
#pragma unroll
            for (int k = 0; k < 14; k++) {
                int gc = tx0 + c4 + k; if (gc > W - 1) gc = W - 1;
                float vx = __ldg(xr + gc), vy = __ldg(yr + gc);
                u64 v  = pack2(vx, vy);
                u64 sp = pack2(fmaf(vx, vx, vy * vy), vx * vy);
#pragma unroll
                for (int q = 0; q < 4; q++) {
                    int t = k - q;
                    if (t >= 0 && t < 11) {
                        aMU[q] = fma2(v,  G2r[t], aMU[q]);
                        aSP[q] = fma2(sp, G2r[t], aSP[q]);
                    }
                }
            }
            int o = r * SH_S + c4;
#pragma unroll
            for (int q = 0; q < 4; q++) {
                sMU[o + q] = aMU[q];
                sSP[o + q] = aSP[q];
            }
        };
        hblur_g(tid);
        if (tid < EH * 8 - 256) hblur_g(tid + 256);
    }
    __syncthreads();

    // ---- pyramid tail: L3 + L4 (sL2 visible via the sync above) --------------
    if (POOL && tid < 16) {
        const u64 QUARTER = pack2(0.25f, 0.25f);
        int rh = tid >> 2, rw = tid & 3;
        const u64* q0 = sL2 + (rh * 2) * 8 + rw * 2;
        u64 v3 = mul2(add2(add2(q0[0], q0[1]), add2(q0[8], q0[9])), QUARTER);
        {
            float a, b; unpack2(v3, a, b);
            size_t po = (size_t)img * 4096 + (size_t)(by * 4 + rh) * 64 + (bx * 4 + rw);
            (Xp + OFF3)[po] = a; (Yp + OFF3)[po] = b;
        }
        u64 s4 = add2(v3, __shfl_xor_sync(0xffffu, v3, 1));
        s4 = add2(s4, __shfl_xor_sync(0xffffu, s4, 4));
        if ((tid & 5) == 0) {
            u64 v4 = mul2(s4, QUARTER);
            int sh = tid >> 3, sw = (tid >> 1) & 1;
            float a, b; unpack2(v4, a, b);
            size_t po = (size_t)img * 1024 + (size_t)(by * 2 + sh) * 32 + (bx * 2 + sw);
            (Xp + OFF4)[po] = a; (Yp + OFF4)[po] = b;
        }
    }

    // ---- vertical blur (4 rows per thread) + epilogue ------------------------
    float d_acc = 0.f, cs_acc = 0.f;
    const int ty = tid >> 5, tx = tid & 31;
    const int rbase = ty * 4;
    {
        u64 aMU[4] = {0,0,0,0}, aSP[4] = {0,0,0,0};
#pragma unroll
        for (int k = 0; k < 14; k++) {
            int row = (rbase + k) * SH_S + tx;
            u64 mu = sMU[row];
            u64 sp = sSP[row];
#pragma unroll
            for (int q = 0; q < 4; q++) {
                int t = k - q;
                if (t >= 0 && t < 11) {
                    aMU[q] = fma2(mu, G2r[t], aMU[q]);
                    aSP[q] = fma2(sp, G2r[t], aSP[q]);
                }
            }
        }
        const int ocol = tx0 + tx;
#pragma unroll
        for (int q = 0; q < 4; q++) {
            int orow = ty0 + rbase + q;
            if (orow < outH && ocol < outH) {
                float mu1, mu2, ess, exy;
                unpack2(aMU[q], mu1, mu2);
                unpack2(aSP[q], ess, exy);
                float mu1sq = mu1 * mu1, mu2sq = mu2 * mu2, mu12 = mu1 * mu2;
                float sig_sum = ess - mu1sq - mu2sq;
                float sig12 = exy - mu12;
                float S1 = __fdividef(2.f * mu12 + C1V, mu1sq + mu2sq + C1V);
                float S2 = __fdividef(2.f * sig12 + C2V, sig_sum + C2V);
                float S = fminf(S1 + S2, 2.0f);
                d_acc += sqrt_fast(2.0f - S);
                cs_acc += S2;
            }
        }
    }

    // ---- block reduce + atomic -----------------------------------------------
#pragma unroll
    for (int o = 16; o > 0; o >>= 1) {
        d_acc  += __shfl_down_sync(0xffffffffu, d_acc,  o);
        cs_acc += __shfl_down_sync(0xffffffffu, cs_acc, o);
    }
    if (tx == 0) { red[0][ty] = d_acc; red[1][ty] = cs_acc; }
    __syncthreads();
    if (tid == 0) {
        float ds = 0.f, cs = 0.f;
#pragma unroll
        for (int j = 0; j < 8; j++) { ds += red[0][j]; cs += red[1][j]; }
        atomicAdd(&d_sums[(level * 48 + img) * 2 + 0], ds);
        atomicAdd(&d_sums[(level * 48 + img) * 2 + 1], cs);
    }
}

__global__ void __launch_bounds__(256) ssim_level0_kernel(
    const float* __restrict__ X, const float* __restrict__ Y,
    float* __restrict__ Xp, float* __restrict__ Yp)
{
    const int img = blockIdx.z;
    const float* Xi = X + (size_t)img * 512 * 512;
    const float* Yi = Y + (size_t)img * 512 * 512;
    ssim_tile<true>(Xi, Yi, 512, 0, img, blockIdx.x, blockIdx.y, Xp, Yp);
}

// levels 1..4 in one grid of 4080 blocks
__global__ void __launch_bounds__(256) ssim_rest_kernel(
    const float* __restrict__ Xp, const float* __restrict__ Yp)
{
    int b = blockIdx.x;
    int level, H, nt, off, base;
    if (b < 3072)      { level = 1; H = 256; nt = 8; off = OFF1; base = 0; }
    else if (b < 3840) { level = 2; H = 128; nt = 4; off = OFF2; base = 3072; }
    else if (b < 4032) { level = 3; H = 64;  nt = 2; off = OFF3; base = 3840; }
    else               { level = 4; H = 32;  nt = 1; off = OFF4; base = 4032; }
    int rem = b - base;
    int tiles = nt * nt;
    int img = rem / tiles;
    int t = rem - img * tiles;
    int by = t / nt;
    int bx = t - by * nt;
    const float* Xi = Xp + off + (size_t)img * H * H;
    const float* Yi = Yp + off + (size_t)img * H * H;
    ssim_tile<false>(Xi, Yi, H, level, img, bx, by, nullptr, nullptr);
}

__global__ void final_kernel(float* out, int out_size)
{
    __shared__ float part[2];
    const int i = threadIdx.x;       // 64 threads
    const float wts[5]  = {0.0448f, 0.2856f, 0.3001f, 0.2363f, 0.1333f};
    const float icnt[5] = {1.f/252004.f, 1.f/60516.f, 1.f/13924.f, 1.f/2916.f, 1.f/484.f};
    float v = 0.f;
    if (i < 48) {
        v = 1.f;
#pragma unroll
        for (int l = 0; l < 4; l++) {
            float csm = fmaxf(d_sums[(l * 48 + i) * 2 + 1] * icnt[l], 0.f);
            v *= __powf(csm, wts[l]);
        }
        float dm = fmaxf(d_sums[(4 * 48 + i) * 2 + 0] * icnt[4], 0.f);
        v *= __powf(dm, wts[4]);
    }
    float s = v;
#pragma unroll
    for (int o = 16; o > 0; o >>= 1) s += __shfl_down_sync(0xffffffffu, s, o);
    if ((i & 31) == 0) part[i >> 5] = s;
    __syncthreads();
    if (i == 0) {
        float r = (part[0] + part[1]) * (1.0f / 48.0f);
        for (int k = 0; k < out_size; k++) out[k] = r;
    }
    // restore invariant: d_sums zeroed for the next kernel_launch call
    __syncthreads();
    for (int j = i; j < 480; j += 64) d_sums[j] = 0.f;
}

extern "C" void kernel_launch(void* const* d_in, const int* in_sizes, int n_in,
                              void* d_out, int out_size)
{
    const float* X = (const float*)d_in[0];
    const float* Y = (const float*)d_in[1];
    float* out = (float*)d_out;

    float *Xp = nullptr, *Yp = nullptr;
    cudaGetSymbolAddress((void**)&Xp, d_Xp);
    cudaGetSymbolAddress((void**)&Yp, d_Yp);

    ssim_level0_kernel<<<dim3(16, 16, 48), 256>>>(X, Y, Xp, Yp);
    ssim_rest_kernel<<<4080, 256>>>(Xp, Yp);
    final_kernel<<<1, 64>>>(out, out_size);
}

// round 15
// speedup vs baseline: 1.1621x; 1.0174x over previous
#include <cuda_runtime.h>
#include <math.h>

// ---------------------------------------------------------------------------
// MS-SSIM, 5 levels, 16x3x512x512 fp32 (48 planes). 3 launches:
//   ssim_level0 (+ fused pool pyramid L1..L4), ssim_rest (levels 1..4),
//   final (parallel combine + re-zero of d_sums).
// R14 core: NO sIN staging; hblur reads its windows directly from global
// (L1-resident tile) via float4 __ldg. SMEM only for h-blurred maps (23KB).
// R15: symmetric 6-entry coefficient array (-10 regs) + launch_bounds(256,6)
// -> 6 blocks/SM (occupancy was register-bound at 5).
// Blur: 2 packed f32x2 streams (x,y) and (x^2+y^2, x*y), all fp32.
// ---------------------------------------------------------------------------

typedef unsigned long long u64;

__device__ __forceinline__ u64 pack2(float lo, float hi) {
    u64 r; asm("mov.b64 %0,{%1,%2};" : "=l"(r) : "f"(lo), "f"(hi)); return r;
}
__device__ __forceinline__ void unpack2(u64 v, float& lo, float& hi) {
    asm("mov.b64 {%0,%1},%2;" : "=f"(lo), "=f"(hi) : "l"(v));
}
__device__ __forceinline__ u64 fma2(u64 a, u64 b, u64 c) {
    u64 d; asm("fma.rn.f32x2 %0,%1,%2,%3;" : "=l"(d) : "l"(a), "l"(b), "l"(c)); return d;
}
__device__ __forceinline__ u64 mul2(u64 a, u64 b) {
    u64 d; asm("mul.rn.f32x2 %0,%1,%2;" : "=l"(d) : "l"(a), "l"(b)); return d;
}
__device__ __forceinline__ u64 add2(u64 a, u64 b) {
    u64 d; asm("add.rn.f32x2 %0,%1,%2;" : "=l"(d) : "l"(a), "l"(b)); return d;
}
__device__ __forceinline__ float sqrt_fast(float x) {
    float r; asm("sqrt.approx.f32 %0,%1;" : "=f"(r) : "f"(x)); return r;
}

#define TW 32
#define TH 32
#define EH 42
#define EW 42
#define SH_S  33       // stride of h-blurred maps

// gaussian(sigma=1.5, 11 taps), normalized
#define G_0 0.00102838f
#define G_1 0.00759876f
#define G_2 0.03600088f
#define G_3 0.10936090f
#define G_4 0.21300530f
#define G_5 0.26601160f
// symmetric coefficient lookup (t is compile-time after full unroll)
#define GQ(t) G2c[(t) < 6 ? (t) : 10 - (t)]

__device__ __align__(16) float d_Xp[4177920];
__device__ __align__(16) float d_Yp[4177920];
__device__ float d_sums[480];   // [level][img][2]  (zero-init; final re-zeros)

#define OFF1 0
#define OFF2 3145728
#define OFF3 3932160
#define OFF4 4128768

#define C1V 1e-4f
#define C2V 9e-4f

// core tile worker. POOL => level 0 (H=512, also emits L1..L4 pyramid).
template <bool POOL>
__device__ __forceinline__ void ssim_tile(
    const float* __restrict__ Xi, const float* __restrict__ Yi,
    int H, int level, int img, int bx, int by,
    float* __restrict__ Xp, float* __restrict__ Yp)
{
    __shared__ u64 sMU[EH * SH_S];    // h-blurred (gx,gy)
    __shared__ u64 sSP[EH * SH_S];    // h-blurred (E[xx+yy], E[xy])
    __shared__ u64 sL2[64];
    __shared__ float red[2][8];

    const int W = H;
    const int outH = H - 10;
    const int tx0 = bx * TW;
    const int ty0 = by * TH;
    const int tid = threadIdx.x;

    const u64 G2c[6] = {pack2(G_0,G_0), pack2(G_1,G_1), pack2(G_2,G_2),
                        pack2(G_3,G_3), pack2(G_4,G_4), pack2(G_5,G_5)};

    // ---- fused pool pyramid (level 0 only): L1, L2 (reads global, L1-hot) ---
    if (POOL) {
        const u64 QUARTER = pack2(0.25f, 0.25f);
        const int lane = tid & 31;
        int ph = tid >> 4, pw = tid & 15;
        const float* xr = Xi + (size_t)(ty0 + 2 * ph) * W + tx0 + 2 * pw;
        const float* yr = Yi + (size_t)(ty0 + 2 * ph) * W + tx0 + 2 * pw;
        float2 a0 = __ldg((const float2*)xr);
        float2 a1 = __ldg((const float2*)(xr + W));
        float2 b0 = __ldg((const float2*)yr);
        float2 b1 = __ldg((const float2*)(yr + W));
        float px = 0.25f * ((a0.x + a0.y) + (a1.x + a1.y));
        float py = 0.25f * ((b0.x + b0.y) + (b1.x + b1.y));
        u64 v1 = pack2(px, py);
        {
            size_t po = (size_t)img * 65536 + (size_t)(by * 16 + ph) * 256 + (bx * 16 + pw);
            (Xp + OFF1)[po] = px; (Yp + OFF1)[po] = py;
        }
        u64 s2 = add2(v1, __shfl_xor_sync(0xffffffffu, v1, 1));
        s2 = add2(s2, __shfl_xor_sync(0xffffffffu, s2, 16));
        if ((lane & 17) == 0) {
            u64 v2 = mul2(s2, QUARTER);
            int qh = tid >> 5, qw = lane >> 1;
            float a, b; unpack2(v2, a, b);
            size_t po = (size_t)img * 16384 + (size_t)(by * 8 + qh) * 128 + (bx * 8 + qw);
            (Xp + OFF2)[po] = a; (Yp + OFF2)[po] = b;
            sL2[qh * 8 + qw] = v2;
        }
    }

    // ---- horizontal blur straight from global: 42 rows x 8 groups of 4 ------
    const bool interior = (tx0 + 44 <= W) && (ty0 + EH <= H);
    if (interior) {
        auto hblur = [&](int item) {
            int r = item >> 3, c4 = (item & 7) << 2;
            const float4* xr = (const float4*)(Xi + (size_t)(ty0 + r) * W + tx0 + c4);
            const float4* yr = (const float4*)(Yi + (size_t)(ty0 + r) * W + tx0 + c4);
            float xs[16], ys[16];
#pragma unroll
            for (int j = 0; j < 4; j++) {
                float4 xv = __ldg(xr + j);
                float4 yv = __ldg(yr + j);
                xs[4*j+0] = xv.x; xs[4*j+1] = xv.y; xs[4*j+2] = xv.z; xs[4*j+3] = xv.w;
                ys[4*j+0] = yv.x; ys[4*j+1] = yv.y; ys[4*j+2] = yv.z; ys[4*j+3] = yv.w;
            }
            u64 aMU[4] = {0,0,0,0}, aSP[4] = {0,0,0,0};
#pragma unroll
            for (int k = 0; k < 14; k++) {
                float vx = xs[k], vy = ys[k];
                u64 v  = pack2(vx, vy);
                u64 sp = pack2(fmaf(vx, vx, vy * vy), vx * vy);
#pragma unroll
                for (int q = 0; q < 4; q++) {
                    int t = k - q;
                    if (t >= 0 && t < 11) {
                        aMU[q] = fma2(v,  GQ(t), aMU[q]);
                        aSP[q] = fma2(sp, GQ(t), aSP[q]);
                    }
                }
            }
            int o = r * SH_S + c4;
#pragma unroll
            for (int q = 0; q < 4; q++) {
                sMU[o + q] = aMU[q];
                sSP[o + q] = aSP[q];
            }
        };
        hblur(tid);
        if (tid < EH * 8 - 256) hblur(tid + 256);
    } else {
        auto hblur_g = [&](int item) {
            int r = item >> 3, c4 = (item & 7) << 2;
            int gr = ty0 + r; if (gr > H - 1) gr = H - 1;
            const float* xr = Xi + (size_t)gr * W;
            const float* yr = Yi + (size_t)gr * W;
            u64 aMU[4] = {0,0,0,0}, aSP[4] = {0,0,0,0};
#pragma unroll
            for (int k = 0; k < 14; k++) {
                int gc = tx0 + c4 + k; if (gc > W - 1) gc = W - 1;
                float vx = __ldg(xr + gc), vy = __ldg(yr + gc);
                u64 v  = pack2(vx, vy);
                u64 sp = pack2(fmaf(vx, vx, vy * vy), vx * vy);
#pragma unroll
                for (int q = 0; q < 4; q++) {
                    int t = k - q;
                    if (t >= 0 && t < 11) {
                        aMU[q] = fma2(v,  GQ(t), aMU[q]);
                        aSP[q] = fma2(sp, GQ(t), aSP[q]);
                    }
                }
            }
            int o = r * SH_S + c4;
#pragma unroll
            for (int q = 0; q < 4; q++) {
                sMU[o + q] = aMU[q];
                sSP[o + q] = aSP[q];
            }
        };
        hblur_g(tid);
        if (tid < EH * 8 - 256) hblur_g(tid + 256);
    }
    __syncthreads();

    // ---- pyramid tail: L3 + L4 (sL2 visible via the sync above) --------------
    if (POOL && tid < 16) {
        const u64 QUARTER = pack2(0.25f, 0.25f);
        int rh = tid >> 2, rw = tid & 3;
        const u64* q0 = sL2 + (rh * 2) * 8 + rw * 2;
        u64 v3 = mul2(add2(add2(q0[0], q0[1]), add2(q0[8], q0[9])), QUARTER);
        {
            float a, b; unpack2(v3, a, b);
            size_t po = (size_t)img * 4096 + (size_t)(by * 4 + rh) * 64 + (bx * 4 + rw);
            (Xp + OFF3)[po] = a; (Yp + OFF3)[po] = b;
        }
        u64 s4 = add2(v3, __shfl_xor_sync(0xffffu, v3, 1));
        s4 = add2(s4, __shfl_xor_sync(0xffffu, s4, 4));
        if ((tid & 5) == 0) {
            u64 v4 = mul2(s4, QUARTER);
            int sh = tid >> 3, sw = (tid >> 1) & 1;
            float a, b; unpack2(v4, a, b);
            size_t po = (size_t)img * 1024 + (size_t)(by * 2 + sh) * 32 + (bx * 2 + sw);
            (Xp + OFF4)[po] = a; (Yp + OFF4)[po] = b;
        }
    }

    // ---- vertical blur (4 rows per thread) + epilogue ------------------------
    float d_acc = 0.f, cs_acc = 0.f;
    const int ty = tid >> 5, tx = tid & 31;
    const int rbase = ty * 4;
    {
        u64 aMU[4] = {0,0,0,0}, aSP[4] = {0,0,0,0};
#pragma unroll
        for (int k = 0; k < 14; k++) {
            int row = (rbase + k) * SH_S + tx;
            u64 mu = sMU[row];
            u64 sp = sSP[row];
#pragma unroll
            for (int q = 0; q < 4; q++) {
                int t = k - q;
                if (t >= 0 && t < 11) {
                    aMU[q] = fma2(mu, GQ(t), aMU[q]);
                    aSP[q] = fma2(sp, GQ(t), aSP[q]);
                }
            }
        }
        const int ocol = tx0 + tx;
#pragma unroll
        for (int q = 0; q < 4; q++) {
            int orow = ty0 + rbase + q;
            if (orow < outH && ocol < outH) {
                float mu1, mu2, ess, exy;
                unpack2(aMU[q], mu1, mu2);
                unpack2(aSP[q], ess, exy);
                float mu1sq = mu1 * mu1, mu2sq = mu2 * mu2, mu12 = mu1 * mu2;
                float sig_sum = ess - mu1sq - mu2sq;
                float sig12 = exy - mu12;
                float S1 = __fdividef(2.f * mu12 + C1V, mu1sq + mu2sq + C1V);
                float S2 = __fdividef(2.f * sig12 + C2V, sig_sum + C2V);
                float S = fminf(S1 + S2, 2.0f);
                d_acc += sqrt_fast(2.0f - S);
                cs_acc += S2;
            }
        }
    }

    // ---- block reduce + atomic -----------------------------------------------
#pragma unroll
    for (int o = 16; o > 0; o >>= 1) {
        d_acc  += __shfl_down_sync(0xffffffffu, d_acc,  o);
        cs_acc += __shfl_down_sync(0xffffffffu, cs_acc, o);
    }
    if (tx == 0) { red[0][ty] = d_acc; red[1][ty] = cs_acc; }
    __syncthreads();
    if (tid == 0) {
        float ds = 0.f, cs = 0.f;
#pragma unroll
        for (int j = 0; j < 8; j++) { ds += red[0][j]; cs += red[1][j]; }
        atomicAdd(&d_sums[(level * 48 + img) * 2 + 0], ds);
        atomicAdd(&d_sums[(level * 48 + img) * 2 + 1], cs);
    }
}

__global__ void __launch_bounds__(256, 6) ssim_level0_kernel(
    const float* __restrict__ X, const float* __restrict__ Y,
    float* __restrict__ Xp, float* __restrict__ Yp)
{
    const int img = blockIdx.z;
    const float* Xi = X + (size_t)img * 512 * 512;
    const float* Yi = Y + (size_t)img * 512 * 512;
    ssim_tile<true>(Xi, Yi, 512, 0, img, blockIdx.x, blockIdx.y, Xp, Yp);
}

// levels 1..4 in one grid of 4080 blocks
__global__ void __launch_bounds__(256, 6) ssim_rest_kernel(
    const float* __restrict__ Xp, const float* __restrict__ Yp)
{
    int b = blockIdx.x;
    int level, H, nt, off, base;
    if (b < 3072)      { level = 1; H = 256; nt = 8; off = OFF1; base = 0; }
    else if (b < 3840) { level = 2; H = 128; nt = 4; off = OFF2; base = 3072; }
    else if (b < 4032) { level = 3; H = 64;  nt = 2; off = OFF3; base = 3840; }
    else               { level = 4; H = 32;  nt = 1; off = OFF4; base = 4032; }
    int rem = b - base;
    int tiles = nt * nt;
    int img = rem / tiles;
    int t = rem - img * tiles;
    int by = t / nt;
    int bx = t - by * nt;
    const float* Xi = Xp + off + (size_t)img * H * H;
    const float* Yi = Yp + off + (size_t)img * H * H;
    ssim_tile<false>(Xi, Yi, H, level, img, bx, by, nullptr, nullptr);
}

__global__ void final_kernel(float* out, int out_size)
{
    __shared__ float part[2];
    const int i = threadIdx.x;       // 64 threads
    const float wts[5]  = {0.0448f, 0.2856f, 0.3001f, 0.2363f, 0.1333f};
    const float icnt[5] = {1.f/252004.f, 1.f/60516.f, 1.f/13924.f, 1.f/2916.f, 1.f/484.f};
    float v = 0.f;
    if (i < 48) {
        v = 1.f;
#pragma unroll
        for (int l = 0; l < 4; l++) {
            float csm = fmaxf(d_sums[(l * 48 + i) * 2 + 1] * icnt[l], 0.f);
            v *= __powf(csm, wts[l]);
        }
        float dm = fmaxf(d_sums[(4 * 48 + i) * 2 + 0] * icnt[4], 0.f);
        v *= __powf(dm, wts[4]);
    }
    float s = v;
#pragma unroll
    for (int o = 16; o > 0; o >>= 1) s += __shfl_down_sync(0xffffffffu, s, o);
    if ((i & 31) == 0) part[i >> 5] = s;
    __syncthreads();
    if (i == 0) {
        float r = (part[0] + part[1]) * (1.0f / 48.0f);
        for (int k = 0; k < out_size; k++) out[k] = r;
    }
    // restore invariant: d_sums zeroed for the next kernel_launch call
    __syncthreads();
    for (int j = i; j < 480; j += 64) d_sums[j] = 0.f;
}

extern "C" void kernel_launch(void* const* d_in, const int* in_sizes, int n_in,
                              void* d_out, int out_size)
{
    const float* X = (const float*)d_in[0];
    const float* Y = (const float*)d_in[1];
    float* out = (float*)d_out;

    float *Xp = nullptr, *Yp = nullptr;
    cudaGetSymbolAddress((void**)&Xp, d_Xp);
    cudaGetSymbolAddress((void**)&Yp, d_Yp);

    ssim_level0_kernel<<<dim3(16, 16, 48), 256>>>(X, Y, Xp, Yp);
    ssim_rest_kernel<<<4080, 256>>>(Xp, Yp);
    final_kernel<<<1, 64>>>(out, out_size);
}

// round 16
// speedup vs baseline: 1.1876x; 1.0220x over previous
#include <cuda_runtime.h>
#include <math.h>

// ---------------------------------------------------------------------------
// MS-SSIM, 5 levels, 16x3x512x512 fp32 (48 planes). TWO launches:
//   ssim_level0: zeroes out; ssim per tile + fused pool pyramid L1..L4.
//   ssim_rest  : levels 1..4; per-image completion counter -> the 85th block
//                of each image performs the weighted combine into out and
//                resets that image's sums/counter (no final kernel).
// R14/15 core: no input staging; hblur reads global directly (L1-resident
// tile) via float4; row clamp keeps the vector path for row-boundary tiles.
// Blur: 2 packed f32x2 streams (x,y) and (x^2+y^2, x*y), all fp32.
// ---------------------------------------------------------------------------

typedef unsigned long long u64;

__device__ __forceinline__ u64 pack2(float lo, float hi) {
    u64 r; asm("mov.b64 %0,{%1,%2};" : "=l"(r) : "f"(lo), "f"(hi)); return r;
}
__device__ __forceinline__ void unpack2(u64 v, float& lo, float& hi) {
    asm("mov.b64 {%0,%1},%2;" : "=f"(lo), "=f"(hi) : "l"(v));
}
__device__ __forceinline__ u64 fma2(u64 a, u64 b, u64 c) {
    u64 d; asm("fma.rn.f32x2 %0,%1,%2,%3;" : "=l"(d) : "l"(a), "l"(b), "l"(c)); return d;
}
__device__ __forceinline__ u64 mul2(u64 a, u64 b) {
    u64 d; asm("mul.rn.f32x2 %0,%1,%2;" : "=l"(d) : "l"(a), "l"(b)); return d;
}
__device__ __forceinline__ u64 add2(u64 a, u64 b) {
    u64 d; asm("add.rn.f32x2 %0,%1,%2;" : "=l"(d) : "l"(a), "l"(b)); return d;
}
__device__ __forceinline__ float sqrt_fast(float x) {
    float r; asm("sqrt.approx.f32 %0,%1;" : "=f"(r) : "f"(x)); return r;
}

#define TW 32
#define TH 32
#define EH 42
#define EW 42
#define SH_S  33       // stride of h-blurred maps

// gaussian(sigma=1.5, 11 taps), normalized
#define G_0 0.00102838f
#define G_1 0.00759876f
#define G_2 0.03600088f
#define G_3 0.10936090f
#define G_4 0.21300530f
#define G_5 0.26601160f
// symmetric coefficient lookup (t is compile-time after full unroll)
#define GQ(t) G2c[(t) < 6 ? (t) : 10 - (t)]

__device__ __align__(16) float d_Xp[4177920];
__device__ __align__(16) float d_Yp[4177920];
__device__ float d_sums[480];       // [level][img][2]  (zero-init; winners re-zero)
__device__ unsigned d_cnt[48];      // per-image completion counters (rest kernel)

#define OFF1 0
#define OFF2 3145728
#define OFF3 3932160
#define OFF4 4128768

#define C1V 1e-4f
#define C2V 9e-4f

// core tile worker. POOL => level 0 (H=512, also emits L1..L4 pyramid).
template <bool POOL>
__device__ __forceinline__ void ssim_tile(
    const float* __restrict__ Xi, const float* __restrict__ Yi,
    int H, int level, int img, int bx, int by,
    float* __restrict__ Xp, float* __restrict__ Yp)
{
    __shared__ u64 sMU[EH * SH_S];    // h-blurred (gx,gy)
    __shared__ u64 sSP[EH * SH_S];    // h-blurred (E[xx+yy], E[xy])
    __shared__ u64 sL2[64];
    __shared__ float red[2][8];

    const int W = H;
    const int outH = H - 10;
    const int tx0 = bx * TW;
    const int ty0 = by * TH;
    const int tid = threadIdx.x;

    const u64 G2c[6] = {pack2(G_0,G_0), pack2(G_1,G_1), pack2(G_2,G_2),
                        pack2(G_3,G_3), pack2(G_4,G_4), pack2(G_5,G_5)};

    // ---- fused pool pyramid (level 0 only): L1, L2 (reads global, L1-hot) ---
    if (POOL) {
        const u64 QUARTER = pack2(0.25f, 0.25f);
        const int lane = tid & 31;
        int ph = tid >> 4, pw = tid & 15;
        const float* xr = Xi + (size_t)(ty0 + 2 * ph) * W + tx0 + 2 * pw;
        const float* yr = Yi + (size_t)(ty0 + 2 * ph) * W + tx0 + 2 * pw;
        float2 a0 = __ldg((const float2*)xr);
        float2 a1 = __ldg((const float2*)(xr + W));
        float2 b0 = __ldg((const float2*)yr);
        float2 b1 = __ldg((const float2*)(yr + W));
        float px = 0.25f * ((a0.x + a0.y) + (a1.x + a1.y));
        float py = 0.25f * ((b0.x + b0.y) + (b1.x + b1.y));
        u64 v1 = pack2(px, py);
        {
            size_t po = (size_t)img * 65536 + (size_t)(by * 16 + ph) * 256 + (bx * 16 + pw);
            (Xp + OFF1)[po] = px; (Yp + OFF1)[po] = py;
        }
        u64 s2 = add2(v1, __shfl_xor_sync(0xffffffffu, v1, 1));
        s2 = add2(s2, __shfl_xor_sync(0xffffffffu, s2, 16));
        if ((lane & 17) == 0) {
            u64 v2 = mul2(s2, QUARTER);
            int qh = tid >> 5, qw = lane >> 1;
            float a, b; unpack2(v2, a, b);
            size_t po = (size_t)img * 16384 + (size_t)(by * 8 + qh) * 128 + (bx * 8 + qw);
            (Xp + OFF2)[po] = a; (Yp + OFF2)[po] = b;
            sL2[qh * 8 + qw] = v2;
        }
    }

    // ---- horizontal blur straight from global: 42 rows x 8 groups of 4 ------
    // Column-interior tiles use float4 loads with a row clamp (covers interior
    // AND row-boundary tiles). Only column-boundary tiles take the scalar path.
    const bool colint = (tx0 + 44 <= W);
    if (colint) {
        auto hblur = [&](int item) {
            int r = item >> 3, c4 = (item & 7) << 2;
            int gr = ty0 + r; if (gr > H - 1) gr = H - 1;
            const float4* xr = (const float4*)(Xi + (size_t)gr * W + tx0 + c4);
            const float4* yr = (const float4*)(Yi + (size_t)gr * W + tx0 + c4);
            float xs[16], ys[16];
#pragma unroll
            for (int j = 0; j < 4; j++) {
                float4 xv = __ldg(xr + j);
                float4 yv = __ldg(yr + j);
                xs[4*j+0] = xv.x; xs[4*j+1] = xv.y; xs[4*j+2] = xv.z; xs[4*j+3] = xv.w;
                ys[4*j+0] = yv.x; ys[4*j+1] = yv.y; ys[4*j+2] = yv.z; ys[4*j+3] = yv.w;
            }
            u64 aMU[4] = {0,0,0,0}, aSP[4] = {0,0,0,0};
#pragma unroll
            for (int k = 0; k < 14; k++) {
                float vx = xs[k], vy = ys[k];
                u64 v  = pack2(vx, vy);
                u64 sp = pack2(fmaf(vx, vx, vy * vy), vx * vy);
#pragma unroll
                for (int q = 0; q < 4; q++) {
                    int t = k - q;
                    if (t >= 0 && t < 11) {
                        aMU[q] = fma2(v,  GQ(t), aMU[q]);
                        aSP[q] = fma2(sp, GQ(t), aSP[q]);
                    }
                }
            }
            int o = r * SH_S + c4;
#pragma unroll
            for (int q = 0; q < 4; q++) {
                sMU[o + q] = aMU[q];
                sSP[o + q] = aSP[q];
            }
        };
        hblur(tid);
        if (tid < EH * 8 - 256) hblur(tid + 256);
    } else {
        auto hblur_g = [&](int item) {
            int r = item >> 3, c4 = (item & 7) << 2;
            int gr = ty0 + r; if (gr > H - 1) gr = H - 1;
            const float* xr = Xi + (size_t)gr * W;
            const float* yr = Yi + (size_t)gr * W;
            u64 aMU[4] = {0,0,0,0}, aSP[4] = {0,0,0,0};
#pragma unroll
            for (int k = 0; k < 14; k++) {
                int gc = tx0 + c4 + k; if (gc > W - 1) gc = W - 1;
                float vx = __ldg(xr + gc), vy = __ldg(yr + gc);
                u64 v  = pack2(vx, vy);
                u64 sp = pack2(fmaf(vx, vx, vy * vy), vx * vy);
#pragma unroll
                for (int q = 0; q < 4; q++) {
                    int t = k - q;
                    if (t >= 0 && t < 11) {
                        aMU[q] = fma2(v,  GQ(t), aMU[q]);
                        aSP[q] = fma2(sp, GQ(t), aSP[q]);
                    }
                }
            }
            int o = r * SH_S + c4;
#pragma unroll
            for (int q = 0; q < 4; q++) {
                sMU[o + q] = aMU[q];
                sSP[o + q] = aSP[q];
            }
        };
        hblur_g(tid);
        if (tid < EH * 8 - 256) hblur_g(tid + 256);
    }
    __syncthreads();

    // ---- pyramid tail: L3 + L4 (sL2 visible via the sync above) --------------
    if (POOL && tid < 16) {
        const u64 QUARTER = pack2(0.25f, 0.25f);
        int rh = tid >> 2, rw = tid & 3;
        const u64* q0 = sL2 + (rh * 2) * 8 + rw * 2;
        u64 v3 = mul2(add2(add2(q0[0], q0[1]), add2(q0[8], q0[9])), QUARTER);
        {
            float a, b; unpack2(v3, a, b);
            size_t po = (size_t)img * 4096 + (size_t)(by * 4 + rh) * 64 + (bx * 4 + rw);
            (Xp + OFF3)[po] = a; (Yp + OFF3)[po] = b;
        }
        u64 s4 = add2(v3, __shfl_xor_sync(0xffffu, v3, 1));
        s4 = add2(s4, __shfl_xor_sync(0xffffu, s4, 4));
        if ((tid & 5) == 0) {
            u64 v4 = mul2(s4, QUARTER);
            int sh = tid >> 3, sw = (tid >> 1) & 1;
            float a, b; unpack2(v4, a, b);
            size_t po = (size_t)img * 1024 + (size_t)(by * 2 + sh) * 32 + (bx * 2 + sw);
            (Xp + OFF4)[po] = a; (Yp + OFF4)[po] = b;
        }
    }

    // ---- vertical blur (4 rows per thread) + epilogue ------------------------
    float d_acc = 0.f, cs_acc = 0.f;
    const int ty = tid >> 5, tx = tid & 31;
    const int rbase = ty * 4;
    {
        u64 aMU[4] = {0,0,0,0}, aSP[4] = {0,0,0,0};
#pragma unroll
        for (int k = 0; k < 14; k++) {
            int row = (rbase + k) * SH_S + tx;
            u64 mu = sMU[row];
            u64 sp = sSP[row];
#pragma unroll
            for (int q = 0; q < 4; q++) {
                int t = k - q;
                if (t >= 0 && t < 11) {
                    aMU[q] = fma2(mu, GQ(t), aMU[q]);
                    aSP[q] = fma2(sp, GQ(t), aSP[q]);
                }
            }
        }
        const int ocol = tx0 + tx;
#pragma unroll
        for (int q = 0; q < 4; q++) {
            int orow = ty0 + rbase + q;
            if (orow < outH && ocol < outH) {
                float mu1, mu2, ess, exy;
                unpack2(aMU[q], mu1, mu2);
                unpack2(aSP[q], ess, exy);
                float mu1sq = mu1 * mu1, mu2sq = mu2 * mu2, mu12 = mu1 * mu2;
                float sig_sum = ess - mu1sq - mu2sq;
                float sig12 = exy - mu12;
                float S1 = __fdividef(2.f * mu12 + C1V, mu1sq + mu2sq + C1V);
                float S2 = __fdividef(2.f * sig12 + C2V, sig_sum + C2V);
                float S = fminf(S1 + S2, 2.0f);
                d_acc += sqrt_fast(2.0f - S);
                cs_acc += S2;
            }
        }
    }

    // ---- block reduce + atomic -----------------------------------------------
#pragma unroll
    for (int o = 16; o > 0; o >>= 1) {
        d_acc  += __shfl_down_sync(0xffffffffu, d_acc,  o);
        cs_acc += __shfl_down_sync(0xffffffffu, cs_acc, o);
    }
    if (tx == 0) { red[0][ty] = d_acc; red[1][ty] = cs_acc; }
    __syncthreads();
    if (tid == 0) {
        float ds = 0.f, cs = 0.f;
#pragma unroll
        for (int j = 0; j < 8; j++) { ds += red[0][j]; cs += red[1][j]; }
        atomicAdd(&d_sums[(level * 48 + img) * 2 + 0], ds);
        atomicAdd(&d_sums[(level * 48 + img) * 2 + 1], cs);
    }
}

__global__ void __launch_bounds__(256, 6) ssim_level0_kernel(
    const float* __restrict__ X, const float* __restrict__ Y,
    float* __restrict__ Xp, float* __restrict__ Yp,
    float* __restrict__ out, int out_size)
{
    // zero the output accumulator (rest kernel's winners atomicAdd into it)
    if (blockIdx.x == 0 && blockIdx.y == 0 && blockIdx.z == 0 &&
        (int)threadIdx.x < out_size) out[threadIdx.x] = 0.f;

    const int img = blockIdx.z;
    const float* Xi = X + (size_t)img * 512 * 512;
    const float* Yi = Y + (size_t)img * 512 * 512;
    ssim_tile<true>(Xi, Yi, 512, 0, img, blockIdx.x, blockIdx.y, Xp, Yp);
}

// levels 1..4 in one grid of 4080 blocks; the 85th finisher per image combines.
__global__ void __launch_bounds__(256, 6) ssim_rest_kernel(
    const float* __restrict__ Xp, const float* __restrict__ Yp,
    float* __restrict__ out, int out_size)
{
    int b = blockIdx.x;
    int level, H, nt, off, base;
    if (b < 3072)      { level = 1; H = 256; nt = 8; off = OFF1; base = 0; }
    else if (b < 3840) { level = 2; H = 128; nt = 4; off = OFF2; base = 3072; }
    else if (b < 4032) { level = 3; H = 64;  nt = 2; off = OFF3; base = 3840; }
    else               { level = 4; H = 32;  nt = 1; off = OFF4; base = 4032; }
    int rem = b - base;
    int tiles = nt * nt;
    int img = rem / tiles;
    int t = rem - img * tiles;
    int by = t / nt;
    int bx = t - by * nt;
    const float* Xi = Xp + off + (size_t)img * H * H;
    const float* Yi = Yp + off + (size_t)img * H * H;
    ssim_tile<false>(Xi, Yi, H, level, img, bx, by, nullptr, nullptr);

    // completion protocol: 85 blocks per image (64+16+4+1). Last one combines.
    if (threadIdx.x == 0) {
        __threadfence();
        unsigned old = atomicAdd(&d_cnt[img], 1u);
        if (old == 84u) {
            __threadfence();
            // read through L2 (atomic RMW) to dodge stale L1 lines
            float cs0 = atomicAdd(&d_sums[(0 * 48 + img) * 2 + 1], 0.f);
            float cs1 = atomicAdd(&d_sums[(1 * 48 + img) * 2 + 1], 0.f);
            float cs2 = atomicAdd(&d_sums[(2 * 48 + img) * 2 + 1], 0.f);
            float cs3 = atomicAdd(&d_sums[(3 * 48 + img) * 2 + 1], 0.f);
            float ds4 = atomicAdd(&d_sums[(4 * 48 + img) * 2 + 0], 0.f);
            float v = 1.f;
            v *= __powf(fmaxf(cs0 * (1.f / 252004.f), 0.f), 0.0448f);
            v *= __powf(fmaxf(cs1 * (1.f / 60516.f),  0.f), 0.2856f);
            v *= __powf(fmaxf(cs2 * (1.f / 13924.f),  0.f), 0.3001f);
            v *= __powf(fmaxf(cs3 * (1.f / 2916.f),   0.f), 0.2363f);
            v *= __powf(fmaxf(ds4 * (1.f / 484.f),    0.f), 0.1333f);
            float contrib = v * (1.0f / 48.0f);
            for (int k = 0; k < out_size; k++) atomicAdd(&out[k], contrib);
            // reset this image's state for the next kernel_launch call
#pragma unroll
            for (int l = 0; l < 5; l++) {
                atomicExch(&d_sums[(l * 48 + img) * 2 + 0], 0.f);
                atomicExch(&d_sums[(l * 48 + img) * 2 + 1], 0.f);
            }
            atomicExch(&d_cnt[img], 0u);
        }
    }
}

extern "C" void kernel_launch(void* const* d_in, const int* in_sizes, int n_in,
                              void* d_out, int out_size)
{
    const float* X = (const float*)d_in[0];
    const float* Y = (const float*)d_in[1];
    float* out = (float*)d_out;

    float *Xp = nullptr, *Yp = nullptr;
    cudaGetSymbolAddress((void**)&Xp, d_Xp);
    cudaGetSymbolAddress((void**)&Yp, d_Yp);

    ssim_level0_kernel<<<dim3(16, 16, 48), 256>>>(X, Y, Xp, Yp, out, out_size);
    ssim_rest_kernel<<<4080, 256>>>(Xp, Yp, out, out_size);
}